// round 3
// baseline (speedup 1.0000x reference)
#include <cuda_runtime.h>

#define BDIM 1024
#define TDIM 4096
#define WSZ 10
#define HID 32
#define NPOS (TDIM - WSZ)          /* 4086 */
#define THREADS 128
#define PPT 4
#define POS_PER_CTA (THREADS * PPT) /* 512 */

__global__ __launch_bounds__(THREADS, 4)
void hurst_mlp_kernel(const float* __restrict__ returns,
                      const float* __restrict__ W1, const float* __restrict__ b1,
                      const float* __restrict__ W2, const float* __restrict__ b2,
                      const float* __restrict__ W3, const float* __restrict__ b3,
                      float* __restrict__ out)
{
    __shared__ float sW1[WSZ * HID];     // [w][j]
    __shared__ float sW2[HID * HID];     // [k][j]
    __shared__ float sW3[HID];
    __shared__ float sb1[HID];
    __shared__ float sb2[HID];
    __shared__ float sxs[POS_PER_CTA + WSZ + 6];

    const int tid = threadIdx.x;
    const int row = blockIdx.y;
    const int p0  = blockIdx.x * POS_PER_CTA;

    for (int i = tid; i < WSZ * HID; i += THREADS) sW1[i] = W1[i];
    for (int i = tid; i < HID * HID; i += THREADS) sW2[i] = W2[i];
    if (tid < HID) { sW3[tid] = W3[tid]; sb1[tid] = b1[tid]; sb2[tid] = b2[tid]; }

    const float* xrow = returns + (long)row * TDIM;
    for (int i = tid; i < POS_PER_CTA + WSZ; i += THREADS) {
        int t = p0 + i;
        sxs[i] = (t < TDIM) ? xrow[t] : 0.0f;
    }
    const float bb3 = b3[0];
    __syncthreads();

    // NOT unrolled: keeps exactly one h1/h2 copy live -> no register spill
    #pragma unroll 1
    for (int r = 0; r < PPT; r++) {
        const int pl = tid + r * THREADS;
        const int p  = p0 + pl;

        // ---- layer 1
        float h1[HID];
        #pragma unroll
        for (int j = 0; j < HID; j++) h1[j] = sb1[j];
        #pragma unroll
        for (int w = 0; w < WSZ; w++) {
            const float xv = sxs[pl + w];
            const float4* wrow = (const float4*)(sW1 + w * HID);
            #pragma unroll
            for (int j4 = 0; j4 < HID / 4; j4++) {
                const float4 wv = wrow[j4];
                h1[4*j4+0] += xv * wv.x;
                h1[4*j4+1] += xv * wv.y;
                h1[4*j4+2] += xv * wv.z;
                h1[4*j4+3] += xv * wv.w;
            }
        }

        // ---- layer 2 (relu applied to h1 on consumption)
        float h2[HID];
        #pragma unroll
        for (int j = 0; j < HID; j++) h2[j] = sb2[j];
        #pragma unroll
        for (int k = 0; k < HID; k++) {
            const float v = fmaxf(h1[k], 0.0f);
            const float4* wrow = (const float4*)(sW2 + k * HID);
            #pragma unroll
            for (int j4 = 0; j4 < HID / 4; j4++) {
                const float4 wv = wrow[j4];
                h2[4*j4+0] += v * wv.x;
                h2[4*j4+1] += v * wv.y;
                h2[4*j4+2] += v * wv.z;
                h2[4*j4+3] += v * wv.w;
            }
        }

        // ---- layer 3 + sigmoid
        float z = bb3;
        const float4* w3v = (const float4*)sW3;
        #pragma unroll
        for (int j4 = 0; j4 < HID / 4; j4++) {
            const float4 wv = w3v[j4];
            z += fmaxf(h2[4*j4+0], 0.0f) * wv.x;
            z += fmaxf(h2[4*j4+1], 0.0f) * wv.y;
            z += fmaxf(h2[4*j4+2], 0.0f) * wv.z;
            z += fmaxf(h2[4*j4+3], 0.0f) * wv.w;
        }
        const float o = 0.5f / (1.0f + __expf(-z));

        if (p < NPOS) {
            out[(long)row * TDIM + WSZ + p] = o;
            if (p == 0) {
                #pragma unroll
                for (int c = 0; c < WSZ; c++)
                    out[(long)row * TDIM + c] = o;
            }
        }
    }
}

extern "C" void kernel_launch(void* const* d_in, const int* in_sizes, int n_in,
                              void* d_out, int out_size)
{
    const float* returns = (const float*)d_in[0];
    const float* W1      = (const float*)d_in[1];
    const float* b1      = (const float*)d_in[2];
    const float* W2      = (const float*)d_in[3];
    const float* b2      = (const float*)d_in[4];
    const float* W3      = (const float*)d_in[5];
    const float* b3      = (const float*)d_in[6];
    float* out           = (float*)d_out;

    dim3 grid((NPOS + POS_PER_CTA - 1) / POS_PER_CTA, BDIM); // (8, 1024)
    hurst_mlp_kernel<<<grid, THREADS>>>(returns, W1, b1, W2, b2, W3, b3, out);
}

// round 7
// speedup vs baseline: 7.0474x; 7.0474x over previous
#include <cuda_runtime.h>

#define BDIM 1024
#define TDIM 4096
#define WSZ 10
#define HID 32
#define NPOS (TDIM - WSZ)          /* 4086 */
#define THREADS 128
#define PPT 4
#define POS_PER_CTA (THREADS * PPT) /* 512 */

__global__ __launch_bounds__(THREADS, 5)
void hurst_mlp_kernel(const float* __restrict__ returns,
                      const float* __restrict__ W1, const float* __restrict__ b1,
                      const float* __restrict__ W2, const float* __restrict__ b2,
                      const float* __restrict__ W3, const float* __restrict__ b3,
                      float* __restrict__ out)
{
    __shared__ float sW1[WSZ * HID];     // [w][j]
    __shared__ float sW2[HID * HID];     // [k][j]
    __shared__ float sW3[HID];
    __shared__ float sb1[HID];
    __shared__ float sb2[HID];
    __shared__ float sxs[POS_PER_CTA + WSZ + 6];

    const int tid = threadIdx.x;
    const int row = blockIdx.y;
    const int p0  = blockIdx.x * POS_PER_CTA;

    for (int i = tid; i < WSZ * HID; i += THREADS) sW1[i] = W1[i];
    for (int i = tid; i < HID * HID; i += THREADS) sW2[i] = W2[i];
    if (tid < HID) { sW3[tid] = W3[tid]; sb1[tid] = b1[tid]; sb2[tid] = b2[tid]; }

    const float* xrow = returns + (long)row * TDIM;
    for (int i = tid; i < POS_PER_CTA + WSZ; i += THREADS) {
        int t = p0 + i;
        sxs[i] = (t < TDIM) ? xrow[t] : 0.0f;
    }
    const float bb3 = b3[0];
    __syncthreads();

    // NOT unrolled: one position's state live at a time
    #pragma unroll 1
    for (int r = 0; r < PPT; r++) {
        const int pl = tid + r * THREADS;
        const int p  = p0 + pl;

        // ---- layer 1: h1 = x @ W1 + b1  (32 accumulators live)
        float h1[HID];
        #pragma unroll
        for (int j = 0; j < HID; j++) h1[j] = sb1[j];
        #pragma unroll
        for (int w = 0; w < WSZ; w++) {
            const float xv = sxs[pl + w];
            const float4* wrow = (const float4*)(sW1 + w * HID);
            #pragma unroll
            for (int j4 = 0; j4 < HID / 4; j4++) {
                const float4 wv = wrow[j4];
                h1[4*j4+0] += xv * wv.x;
                h1[4*j4+1] += xv * wv.y;
                h1[4*j4+2] += xv * wv.z;
                h1[4*j4+3] += xv * wv.w;
            }
        }
        // relu in place (consumed many times below)
        #pragma unroll
        for (int j = 0; j < HID; j++) h1[j] = fmaxf(h1[j], 0.0f);

        // ---- layers 2+3 fused, chunked: 4 chunks of 8 h2-outputs.
        // Each chunk's 8 accumulators are reduced into z immediately and freed.
        float z = bb3;
        #pragma unroll 1
        for (int c = 0; c < 4; c++) {
            const float* w2c = sW2 + c * 8;     // column offset of this chunk
            float acc[8];
            #pragma unroll
            for (int j = 0; j < 8; j++) acc[j] = sb2[c * 8 + j];

            #pragma unroll
            for (int k = 0; k < HID; k++) {
                const float v = h1[k];
                const float4 wa = *(const float4*)(w2c + k * HID);
                const float4 wb = *(const float4*)(w2c + k * HID + 4);
                acc[0] += v * wa.x;  acc[1] += v * wa.y;
                acc[2] += v * wa.z;  acc[3] += v * wa.w;
                acc[4] += v * wb.x;  acc[5] += v * wb.y;
                acc[6] += v * wb.z;  acc[7] += v * wb.w;
            }

            const float4 w3a = *(const float4*)(sW3 + c * 8);
            const float4 w3b = *(const float4*)(sW3 + c * 8 + 4);
            z += fmaxf(acc[0], 0.0f) * w3a.x;
            z += fmaxf(acc[1], 0.0f) * w3a.y;
            z += fmaxf(acc[2], 0.0f) * w3a.z;
            z += fmaxf(acc[3], 0.0f) * w3a.w;
            z += fmaxf(acc[4], 0.0f) * w3b.x;
            z += fmaxf(acc[5], 0.0f) * w3b.y;
            z += fmaxf(acc[6], 0.0f) * w3b.z;
            z += fmaxf(acc[7], 0.0f) * w3b.w;
        }

        const float o = 0.5f / (1.0f + __expf(-z));

        if (p < NPOS) {
            out[(long)row * TDIM + WSZ + p] = o;
            if (p == 0) {
                #pragma unroll
                for (int c = 0; c < WSZ; c++)
                    out[(long)row * TDIM + c] = o;
            }
        }
    }
}

extern "C" void kernel_launch(void* const* d_in, const int* in_sizes, int n_in,
                              void* d_out, int out_size)
{
    const float* returns = (const float*)d_in[0];
    const float* W1      = (const float*)d_in[1];
    const float* b1      = (const float*)d_in[2];
    const float* W2      = (const float*)d_in[3];
    const float* b2      = (const float*)d_in[4];
    const float* W3      = (const float*)d_in[5];
    const float* b3      = (const float*)d_in[6];
    float* out           = (float*)d_out;

    dim3 grid((NPOS + POS_PER_CTA - 1) / POS_PER_CTA, BDIM); // (8, 1024)
    hurst_mlp_kernel<<<grid, THREADS>>>(returns, W1, b1, W2, b2, W3, b3, out);
}

// round 11
// speedup vs baseline: 8.4580x; 1.2002x over previous
#include <cuda_runtime.h>

#define BDIM 1024
#define TDIM 4096
#define WSZ 10
#define HID 32
#define NPOS (TDIM - WSZ)            /* 4086 */
#define THREADS 128
#define PAIRS 2                      /* pair-iterations per thread */
#define POS_PER_CTA (THREADS * PAIRS * 2) /* 512 */
#define HALF (THREADS * PAIRS)       /* 256: offset between A and B streams */

__global__ __launch_bounds__(THREADS, 4)
void hurst_mlp_kernel(const float* __restrict__ returns,
                      const float* __restrict__ W1, const float* __restrict__ b1,
                      const float* __restrict__ W2, const float* __restrict__ b2,
                      const float* __restrict__ W3, const float* __restrict__ b3,
                      float* __restrict__ out)
{
    __shared__ float sW1[WSZ * HID];     // [w][j]
    __shared__ float sW2[HID * HID];     // [k][j]
    __shared__ float sW3[HID];
    __shared__ float sb1[HID];
    __shared__ float sb2[HID];
    __shared__ float sxs[POS_PER_CTA + WSZ + 6];

    const int tid = threadIdx.x;
    const int row = blockIdx.y;
    const int p0  = blockIdx.x * POS_PER_CTA;

    for (int i = tid; i < WSZ * HID; i += THREADS) sW1[i] = W1[i];
    for (int i = tid; i < HID * HID; i += THREADS) sW2[i] = W2[i];
    if (tid < HID) { sW3[tid] = W3[tid]; sb1[tid] = b1[tid]; sb2[tid] = b2[tid]; }

    const float* xrow = returns + (long)row * TDIM;
    for (int i = tid; i < POS_PER_CTA + WSZ; i += THREADS) {
        int t = p0 + i;
        sxs[i] = (t < TDIM) ? xrow[t] : 0.0f;
    }
    const float bb3 = b3[0];
    __syncthreads();

    // Each iteration computes TWO positions (A at pl, B at pl+HALF) sharing
    // every weight LDS between them. NOT unrolled: one pair's state live.
    #pragma unroll 1
    for (int r = 0; r < PAIRS; r++) {
        const int plA = tid + r * THREADS;       // 0..255
        const int plB = plA + HALF;              // 256..511
        const int pA  = p0 + plA;
        const int pB  = p0 + plB;

        // ---- layer 1: both positions, shared W1 loads
        float h1A[HID], h1B[HID];
        #pragma unroll
        for (int j = 0; j < HID; j++) { h1A[j] = sb1[j]; h1B[j] = sb1[j]; }
        #pragma unroll
        for (int w = 0; w < WSZ; w++) {
            const float xA = sxs[plA + w];
            const float xB = sxs[plB + w];
            const float4* wrow = (const float4*)(sW1 + w * HID);
            #pragma unroll
            for (int j4 = 0; j4 < HID / 4; j4++) {
                const float4 wv = wrow[j4];
                h1A[4*j4+0] += xA * wv.x;  h1B[4*j4+0] += xB * wv.x;
                h1A[4*j4+1] += xA * wv.y;  h1B[4*j4+1] += xB * wv.y;
                h1A[4*j4+2] += xA * wv.z;  h1B[4*j4+2] += xB * wv.z;
                h1A[4*j4+3] += xA * wv.w;  h1B[4*j4+3] += xB * wv.w;
            }
        }
        // relu once, in place
        #pragma unroll
        for (int j = 0; j < HID; j++) {
            h1A[j] = fmaxf(h1A[j], 0.0f);
            h1B[j] = fmaxf(h1B[j], 0.0f);
        }

        // ---- layers 2+3 fused, chunked over output dim (4 chunks of 8),
        //      both positions share every W2/W3 load.
        float zA = bb3, zB = bb3;
        #pragma unroll 1
        for (int c = 0; c < 4; c++) {
            const float* w2c = sW2 + c * 8;
            float accA[8], accB[8];
            #pragma unroll
            for (int j = 0; j < 8; j++) { accA[j] = sb2[c*8 + j]; accB[j] = accA[j]; }

            #pragma unroll
            for (int k = 0; k < HID; k++) {
                const float vA = h1A[k];
                const float vB = h1B[k];
                const float4 wa = *(const float4*)(w2c + k * HID);
                const float4 wb = *(const float4*)(w2c + k * HID + 4);
                accA[0] += vA * wa.x;  accB[0] += vB * wa.x;
                accA[1] += vA * wa.y;  accB[1] += vB * wa.y;
                accA[2] += vA * wa.z;  accB[2] += vB * wa.z;
                accA[3] += vA * wa.w;  accB[3] += vB * wa.w;
                accA[4] += vA * wb.x;  accB[4] += vB * wb.x;
                accA[5] += vA * wb.y;  accB[5] += vB * wb.y;
                accA[6] += vA * wb.z;  accB[6] += vB * wb.z;
                accA[7] += vA * wb.w;  accB[7] += vB * wb.w;
            }

            const float4 w3a = *(const float4*)(sW3 + c * 8);
            const float4 w3b = *(const float4*)(sW3 + c * 8 + 4);
            zA += fmaxf(accA[0], 0.0f) * w3a.x;  zB += fmaxf(accB[0], 0.0f) * w3a.x;
            zA += fmaxf(accA[1], 0.0f) * w3a.y;  zB += fmaxf(accB[1], 0.0f) * w3a.y;
            zA += fmaxf(accA[2], 0.0f) * w3a.z;  zB += fmaxf(accB[2], 0.0f) * w3a.z;
            zA += fmaxf(accA[3], 0.0f) * w3a.w;  zB += fmaxf(accB[3], 0.0f) * w3a.w;
            zA += fmaxf(accA[4], 0.0f) * w3b.x;  zB += fmaxf(accB[4], 0.0f) * w3b.x;
            zA += fmaxf(accA[5], 0.0f) * w3b.y;  zB += fmaxf(accB[5], 0.0f) * w3b.y;
            zA += fmaxf(accA[6], 0.0f) * w3b.z;  zB += fmaxf(accB[6], 0.0f) * w3b.z;
            zA += fmaxf(accA[7], 0.0f) * w3b.w;  zB += fmaxf(accB[7], 0.0f) * w3b.w;
        }

        const float oA = 0.5f / (1.0f + __expf(-zA));
        const float oB = 0.5f / (1.0f + __expf(-zB));

        if (pA < NPOS) {
            out[(long)row * TDIM + WSZ + pA] = oA;
            if (pA == 0) {
                #pragma unroll
                for (int c = 0; c < WSZ; c++)
                    out[(long)row * TDIM + c] = oA;
            }
        }
        if (pB < NPOS) {
            out[(long)row * TDIM + WSZ + pB] = oB;
        }
    }
}

extern "C" void kernel_launch(void* const* d_in, const int* in_sizes, int n_in,
                              void* d_out, int out_size)
{
    const float* returns = (const float*)d_in[0];
    const float* W1      = (const float*)d_in[1];
    const float* b1      = (const float*)d_in[2];
    const float* W2      = (const float*)d_in[3];
    const float* b2      = (const float*)d_in[4];
    const float* W3      = (const float*)d_in[5];
    const float* b3      = (const float*)d_in[6];
    float* out           = (float*)d_out;

    dim3 grid((NPOS + POS_PER_CTA - 1) / POS_PER_CTA, BDIM); // (8, 1024)
    hurst_mlp_kernel<<<grid, THREADS>>>(returns, W1, b1, W2, b2, W3, b3, out);
}

// round 12
// speedup vs baseline: 9.3890x; 1.1101x over previous
#include <cuda_runtime.h>

#define BDIM 1024
#define TDIM 4096
#define WSZ 10
#define HID 32
#define NPOS (TDIM - WSZ)            /* 4086 */
#define THREADS 128
#define PAIRS 2
#define POS_PER_CTA (THREADS * PAIRS * 2) /* 512 */
#define HALF (THREADS * PAIRS)       /* 256 */

typedef unsigned long long ull;

__device__ __forceinline__ ull pk2(float lo, float hi) {
    ull r;
    asm("mov.b64 %0, {%1, %2};" : "=l"(r) : "f"(lo), "f"(hi));
    return r;
}
__device__ __forceinline__ void upk2(ull p, float& lo, float& hi) {
    asm("mov.b64 {%0, %1}, %2;" : "=f"(lo), "=f"(hi) : "l"(p));
}
__device__ __forceinline__ ull fma2(ull a, ull b, ull c) {
    ull d;
    asm("fma.rn.f32x2 %0, %1, %2, %3;" : "=l"(d) : "l"(a), "l"(b), "l"(c));
    return d;
}

__global__ __launch_bounds__(THREADS, 3)
void hurst_mlp_kernel(const float* __restrict__ returns,
                      const float* __restrict__ W1, const float* __restrict__ b1,
                      const float* __restrict__ W2, const float* __restrict__ b2,
                      const float* __restrict__ W3, const float* __restrict__ b3,
                      float* __restrict__ out)
{
    __shared__ __align__(16) float sW1[WSZ * HID];   // [w][j]
    __shared__ __align__(16) float sW2[HID * HID];   // [k][j]
    __shared__ __align__(16) float sW3[HID];
    __shared__ __align__(16) float sb1[HID];
    __shared__ __align__(16) float sb2[HID];
    __shared__ __align__(16) float sxs[POS_PER_CTA + WSZ + 6];

    const int tid = threadIdx.x;
    const int row = blockIdx.y;
    const int p0  = blockIdx.x * POS_PER_CTA;

    for (int i = tid; i < WSZ * HID; i += THREADS) sW1[i] = W1[i];
    for (int i = tid; i < HID * HID; i += THREADS) sW2[i] = W2[i];
    if (tid < HID) { sW3[tid] = W3[tid]; sb1[tid] = b1[tid]; sb2[tid] = b2[tid]; }

    const float* xrow = returns + (long)row * TDIM;
    for (int i = tid; i < POS_PER_CTA + WSZ; i += THREADS) {
        int t = p0 + i;
        sxs[i] = (t < TDIM) ? xrow[t] : 0.0f;
    }
    const float bb3 = b3[0];
    __syncthreads();

    #pragma unroll 1
    for (int r = 0; r < PAIRS; r++) {
        const int plA = tid + r * THREADS;
        const int plB = plA + HALF;
        const int pA  = p0 + plA;
        const int pB  = p0 + plB;

        // ---- layer 1 (packed f32x2 over j): h1 = x @ W1 + b1, two streams share W1 loads
        ull h1A[HID/2], h1B[HID/2];
        {
            const ulonglong2* bp = (const ulonglong2*)sb1;     // 8x ulonglong2 = 32 floats
            #pragma unroll
            for (int q = 0; q < HID/4; q++) {
                ulonglong2 bv = bp[q];
                h1A[2*q]   = bv.x;  h1A[2*q+1] = bv.y;
                h1B[2*q]   = bv.x;  h1B[2*q+1] = bv.y;
            }
        }
        #pragma unroll
        for (int w = 0; w < WSZ; w++) {
            const float xA = sxs[plA + w];
            const float xB = sxs[plB + w];
            const ull xpA = pk2(xA, xA);
            const ull xpB = pk2(xB, xB);
            const ulonglong2* wrow = (const ulonglong2*)(sW1 + w * HID); // 8 per row
            #pragma unroll
            for (int q = 0; q < HID/4; q++) {
                const ulonglong2 wv = wrow[q];
                h1A[2*q]   = fma2(xpA, wv.x, h1A[2*q]);
                h1A[2*q+1] = fma2(xpA, wv.y, h1A[2*q+1]);
                h1B[2*q]   = fma2(xpB, wv.x, h1B[2*q]);
                h1B[2*q+1] = fma2(xpB, wv.y, h1B[2*q+1]);
            }
        }

        // unpack + relu once (h1 regs die here; vA/vB take their place)
        float vA[HID], vB[HID];
        #pragma unroll
        for (int q = 0; q < HID/2; q++) {
            float lo, hi;
            upk2(h1A[q], lo, hi);
            vA[2*q]   = fmaxf(lo, 0.0f);
            vA[2*q+1] = fmaxf(hi, 0.0f);
            upk2(h1B[q], lo, hi);
            vB[2*q]   = fmaxf(lo, 0.0f);
            vB[2*q+1] = fmaxf(hi, 0.0f);
        }

        // ---- layers 2+3 fused, 2 chunks of 16 outputs, packed f32x2
        float zA = bb3, zB = bb3;
        #pragma unroll 1
        for (int c = 0; c < 2; c++) {
            ull accA[8], accB[8];
            {
                const ulonglong2* bp = (const ulonglong2*)(sb2 + c * 16); // 4x
                #pragma unroll
                for (int q = 0; q < 4; q++) {
                    ulonglong2 bv = bp[q];
                    accA[2*q]   = bv.x;  accA[2*q+1] = bv.y;
                    accB[2*q]   = bv.x;  accB[2*q+1] = bv.y;
                }
            }

            #pragma unroll
            for (int k = 0; k < HID; k++) {
                const ull vpA = pk2(vA[k], vA[k]);
                const ull vpB = pk2(vB[k], vB[k]);
                const ulonglong2* w2r = (const ulonglong2*)(sW2 + k * HID + c * 16); // 4x
                #pragma unroll
                for (int q = 0; q < 4; q++) {
                    const ulonglong2 wv = w2r[q];
                    accA[2*q]   = fma2(vpA, wv.x, accA[2*q]);
                    accA[2*q+1] = fma2(vpA, wv.y, accA[2*q+1]);
                    accB[2*q]   = fma2(vpB, wv.x, accB[2*q]);
                    accB[2*q+1] = fma2(vpB, wv.y, accB[2*q+1]);
                }
            }

            const float* w3c = sW3 + c * 16;
            #pragma unroll
            for (int q = 0; q < 8; q++) {
                float lo, hi;
                upk2(accA[q], lo, hi);
                zA += fmaxf(lo, 0.0f) * w3c[2*q];
                zA += fmaxf(hi, 0.0f) * w3c[2*q+1];
                upk2(accB[q], lo, hi);
                zB += fmaxf(lo, 0.0f) * w3c[2*q];
                zB += fmaxf(hi, 0.0f) * w3c[2*q+1];
            }
        }

        const float oA = 0.5f / (1.0f + __expf(-zA));
        const float oB = 0.5f / (1.0f + __expf(-zB));

        if (pA < NPOS) {
            out[(long)row * TDIM + WSZ + pA] = oA;
            if (pA == 0) {
                #pragma unroll
                for (int c = 0; c < WSZ; c++)
                    out[(long)row * TDIM + c] = oA;
            }
        }
        if (pB < NPOS) {
            out[(long)row * TDIM + WSZ + pB] = oB;
        }
    }
}

extern "C" void kernel_launch(void* const* d_in, const int* in_sizes, int n_in,
                              void* d_out, int out_size)
{
    const float* returns = (const float*)d_in[0];
    const float* W1      = (const float*)d_in[1];
    const float* b1      = (const float*)d_in[2];
    const float* W2      = (const float*)d_in[3];
    const float* b2      = (const float*)d_in[4];
    const float* W3      = (const float*)d_in[5];
    const float* b3      = (const float*)d_in[6];
    float* out           = (float*)d_out;

    dim3 grid((NPOS + POS_PER_CTA - 1) / POS_PER_CTA, BDIM); // (8, 1024)
    hurst_mlp_kernel<<<grid, THREADS>>>(returns, W1, b1, W2, b2, W3, b3, out);
}